// round 5
// baseline (speedup 1.0000x reference)
#include <cuda_runtime.h>
#include <math.h>
#include <stdint.h>

// Problem constants
#define Bsz 8
#define Hd  512
#define Ls  4096
#define Nm  32

// Scratch (allocation-free rule: __device__ globals)
__device__ float    g_lr[Hd * Nm];
__device__ float    g_li[Hd * Nm];
__device__ float    g_wr[Hd * Nm];
__device__ float    g_wi[Hd * Nm];
__device__ uint32_t g_Wt[2 * Hd * Hd];              // W pre-converted to tf32 bits (1024x512)
__device__ uint32_t g_y[(size_t)Bsz * Hd * Ls];     // post-snake2 activations, tf32 bits (B,H,L)

// ---------------------------------------------------------------------------
// Kernel 1: discretization params.  lambda = exp(dt*A), w = 2*C*(lambda-1)/A
// ---------------------------------------------------------------------------
__global__ void param_kernel(const float* __restrict__ log_dt,
                             const float* __restrict__ Ar,
                             const float* __restrict__ Ai,
                             const float* __restrict__ Cr,
                             const float* __restrict__ Ci)
{
    int i = blockIdx.x * blockDim.x + threadIdx.x;
    if (i >= Hd * Nm) return;
    int h = i >> 5;
    float dt = expf(log_dt[h]);
    float ar = Ar[i], ai = Ai[i];
    float er = expf(dt * ar);
    float lr = er * cosf(dt * ai);
    float li = er * sinf(dt * ai);
    // q = (lambda - 1) / A
    float nr = lr - 1.0f, ni = li;
    float inv = 1.0f / (ar * ar + ai * ai);
    float qr = (nr * ar + ni * ai) * inv;
    float qi = (ni * ar - nr * ai) * inv;
    float cr = Cr[i], ci = Ci[i];
    g_lr[i] = lr;
    g_li[i] = li;
    g_wr[i] = 2.0f * (cr * qr - ci * qi);
    g_wi[i] = 2.0f * (cr * qi + ci * qr);
}

// ---------------------------------------------------------------------------
// Kernel 1b: W -> tf32 (round-to-nearest) once; reused by every GEMM block.
// ---------------------------------------------------------------------------
__global__ void wconv_kernel(const float* __restrict__ W)
{
    int i = blockIdx.x * blockDim.x + threadIdx.x;
    if (i >= 2 * Hd * Hd) return;
    uint32_t b;
    asm("cvt.rna.tf32.f32 %0, %1;" : "=r"(b) : "f"(W[i]));
    g_Wt[i] = b;
}

// ---------------------------------------------------------------------------
// Kernel 2: snake1 -> diagonal SSM scan -> +u*D -> snake2 -> g_y (tf32 bits)
// One warp per (b,h) sequence; lane = complex mode n.
// Per 32-step chunk: 32 broadcast shfl + 31 tree-reduce shfl (vs 192 before).
// ---------------------------------------------------------------------------
__global__ __launch_bounds__(256)
void scan_kernel(const float* __restrict__ x,
                 const float* __restrict__ alpha1,
                 const float* __restrict__ alpha2,
                 const float* __restrict__ Dp)
{
    int warp = (blockIdx.x * blockDim.x + threadIdx.x) >> 5;
    int lane = threadIdx.x & 31;
    int b = warp >> 9;          // / Hd
    int h = warp & (Hd - 1);

    int pidx = (h << 5) + lane;
    float lr = g_lr[pidx];
    float li = g_li[pidx];
    float wr = g_wr[pidx];
    float wi = g_wi[pidx];

    float a1 = alpha1[h];
    float inv1 = 1.0f / (a1 + 1e-9f);
    float a2 = alpha2[h];
    float inv2 = 1.0f / (a2 + 1e-9f);
    float d = Dp[h];

    const float* xp = x + ((size_t)b * Hd + h) * Ls;
    uint32_t*    yp = g_y + ((size_t)b * Hd + h) * Ls;

    float sr = 0.0f, si = 0.0f;

    for (int l0 = 0; l0 < Ls; l0 += 32) {
        float xv = xp[l0 + lane];
        float sn = sinf(a1 * xv);
        float u  = fmaf(sn * sn, inv1, xv);     // snake1

        float v[32];
        #pragma unroll
        for (int j = 0; j < 32; ++j) {
            float uj = __shfl_sync(0xffffffffu, u, j);
            // s = lambda * s + u   (complex)
            float nsr = fmaf(-li, si, fmaf(lr, sr, uj));
            float nsi = fmaf(lr, si, li * sr);
            sr = nsr; si = nsi;
            // per-lane partial of y[l0+j]:  Re(w * s)
            v[j] = fmaf(wr, sr, -wi * si);
        }

        // Cross-lane vector tree reduction: after 5 levels, lane j holds
        // sum over lanes of v[.][j] in v[0].
        #pragma unroll
        for (int off = 16; off >= 1; off >>= 1) {
            bool up = (lane & off) != 0;
            #pragma unroll
            for (int k = 0; k < 32; ++k) {
                if (k >= off) break;           // compile-time pruned
                float send = up ? v[k] : v[k + off];
                float recv = __shfl_xor_sync(0xffffffffu, send, off);
                float keep = up ? v[k + off] : v[k];
                v[k] = keep + recv;
            }
        }

        float yv = fmaf(u, d, v[0]);            // skip connection (lane = timestep)
        float s2 = sinf(a2 * yv);
        yv = fmaf(s2 * s2, inv2, yv);           // snake2
        uint32_t bits;
        asm("cvt.rna.tf32.f32 %0, %1;" : "=r"(bits) : "f"(yv));
        yp[l0 + lane] = bits;                   // store tf32-rounded for GEMM
    }
}

// ---------------------------------------------------------------------------
// Kernel 3: fused 1x1 conv GEMM (tf32 mma.sync) + GLU + residual
// Z = W(1024x512) @ Y_b(512x4096); out = x + (Za+ba)*sigmoid(Zb+bb)
// Block: 64 output channels (paired with rows +512), 128 l-cols, BK=16,
// cp.async double-buffered. 8 warps in 2(M) x 4(N) layout, warp tile 32x32.
// ---------------------------------------------------------------------------
#define BK 16
#define SWS (BK + 4)     // sW stride (words) -> conflict-free A-frag LDS
#define SYS (128 + 8)    // sY stride (words) -> conflict-free B-frag LDS

__device__ __forceinline__ void cp_async16(uint32_t smem, const void* gmem) {
    asm volatile("cp.async.cg.shared.global [%0], [%1], 16;\n" :: "r"(smem), "l"(gmem));
}
__device__ __forceinline__ void cp_commit() {
    asm volatile("cp.async.commit_group;\n");
}
template <int N> __device__ __forceinline__ void cp_wait() {
    asm volatile("cp.async.wait_group %0;\n" :: "n"(N));
}

__device__ __forceinline__ void mma_tf32(float* c,
                                         uint32_t a0, uint32_t a1, uint32_t a2, uint32_t a3,
                                         uint32_t b0, uint32_t b1)
{
    asm volatile(
        "mma.sync.aligned.m16n8k8.row.col.f32.tf32.tf32.f32 "
        "{%0,%1,%2,%3}, {%4,%5,%6,%7}, {%8,%9}, {%0,%1,%2,%3};\n"
        : "+f"(c[0]), "+f"(c[1]), "+f"(c[2]), "+f"(c[3])
        : "r"(a0), "r"(a1), "r"(a2), "r"(a3), "r"(b0), "r"(b1));
}

__global__ __launch_bounds__(256, 2)
void gemm_glu_kernel(const float* __restrict__ bias,
                     const float* __restrict__ X,
                     float* __restrict__ out)
{
    // sW rows 0..63 = W[r0 + row], rows 64..127 = W[r0 + 512 + (row-64)]
    __shared__ uint32_t sW[2][128][SWS];
    __shared__ uint32_t sY[2][BK][SYS];

    const int tid = threadIdx.x;
    const int lane = tid & 31;
    const int wid = tid >> 5;
    const int wm = wid >> 2;          // 0..1
    const int wn = wid & 3;           // 0..3
    const int t4 = lane & 3;
    const int g  = lane >> 2;

    const int l0 = blockIdx.x * 128;
    const int r0 = blockIdx.y * 64;
    const int bb = blockIdx.z;

    const uint32_t* Yb = g_y + (size_t)bb * Hd * Ls;

    const uint32_t swb = (uint32_t)__cvta_generic_to_shared(&sW[0][0][0]);
    const uint32_t syb = (uint32_t)__cvta_generic_to_shared(&sY[0][0][0]);

    // per-thread load slots (2 float4 each for W and Y per chunk)
    int wf0 = tid, wf1 = tid + 256;   // f4 ids 0..511
    int wrow0 = wf0 >> 2, wc0 = (wf0 & 3) << 2;
    int wrow1 = wf1 >> 2, wc1 = (wf1 & 3) << 2;
    int wsrc0 = (r0 + wrow0 + (wrow0 >= 64 ? 448 : 0)) * Hd;
    int wsrc1 = (r0 + wrow1 + (wrow1 >= 64 ? 448 : 0)) * Hd;
    int yk0 = wf0 >> 5, yc0 = (wf0 & 31) << 2;
    int yk1 = wf1 >> 5, yc1 = (wf1 & 31) << 2;

    float acc[2][2][4][4];
    #pragma unroll
    for (int a = 0; a < 2; ++a)
        #pragma unroll
        for (int m = 0; m < 2; ++m)
            #pragma unroll
            for (int n = 0; n < 4; ++n)
                #pragma unroll
                for (int q = 0; q < 4; ++q) acc[a][m][n][q] = 0.0f;

    #define LOAD_CHUNK(KC, BUF) do {                                              \
        int _k0 = (KC) * BK;                                                      \
        cp_async16(swb + (((BUF)*128 + wrow0) * SWS + wc0) * 4,                   \
                   g_Wt + wsrc0 + _k0 + wc0);                                     \
        cp_async16(swb + (((BUF)*128 + wrow1) * SWS + wc1) * 4,                   \
                   g_Wt + wsrc1 + _k0 + wc1);                                     \
        cp_async16(syb + (((BUF)*BK + yk0) * SYS + yc0) * 4,                      \
                   Yb + (size_t)(_k0 + yk0) * Ls + l0 + yc0);                     \
        cp_async16(syb + (((BUF)*BK + yk1) * SYS + yc1) * 4,                      \
                   Yb + (size_t)(_k0 + yk1) * Ls + l0 + yc1);                     \
    } while (0)

    LOAD_CHUNK(0, 0); cp_commit();
    LOAD_CHUNK(1, 1); cp_commit();

    const int NCH = Hd / BK;   // 32 chunks
    #pragma unroll 1
    for (int kc = 0; kc < NCH; ++kc) {
        if (kc < NCH - 1) cp_wait<1>(); else cp_wait<0>();
        __syncthreads();
        int buf = kc & 1;

        #pragma unroll
        for (int ks = 0; ks < 2; ++ks) {
            int kk = ks * 8 + t4;
            uint32_t B0[4], B1[4];
            #pragma unroll
            for (int ni = 0; ni < 4; ++ni) {
                int col = wn * 32 + ni * 8 + g;
                B0[ni] = sY[buf][kk][col];
                B1[ni] = sY[buf][kk + 4][col];
            }
            #pragma unroll
            for (int half = 0; half < 2; ++half) {
                #pragma unroll
                for (int mi = 0; mi < 2; ++mi) {
                    int rb = half * 64 + wm * 32 + mi * 16 + g;
                    uint32_t a0 = sW[buf][rb][kk];
                    uint32_t a1 = sW[buf][rb + 8][kk];
                    uint32_t a2 = sW[buf][rb][kk + 4];
                    uint32_t a3 = sW[buf][rb + 8][kk + 4];
                    #pragma unroll
                    for (int ni = 0; ni < 4; ++ni)
                        mma_tf32(acc[half][mi][ni], a0, a1, a2, a3, B0[ni], B1[ni]);
                }
            }
        }
        __syncthreads();
        if (kc + 2 < NCH) { LOAD_CHUNK(kc + 2, buf); cp_commit(); }
    }
    #undef LOAD_CHUNK

    // Epilogue: bias + GLU + residual
    const float* Xb = X   + (size_t)bb * Hd * Ls;
    float*       Ob = out + (size_t)bb * Hd * Ls;

    #pragma unroll
    for (int mi = 0; mi < 2; ++mi) {
        int o = r0 + wm * 32 + mi * 16 + g;
        float ba0 = bias[o];
        float bB0 = bias[o + 512];
        float ba8 = bias[o + 8];
        float bB8 = bias[o + 520];
        #pragma unroll
        for (int ni = 0; ni < 4; ++ni) {
            int l = l0 + wn * 32 + ni * 8 + 2 * t4;
            const float* A = acc[0][mi][ni];
            const float* Bc = acc[1][mi][ni];

            float2 xv0 = *(const float2*)(Xb + (size_t)o * Ls + l);
            float2 xv8 = *(const float2*)(Xb + (size_t)(o + 8) * Ls + l);

            float av, bv, sg;
            float2 ov0, ov8;
            av = A[0] + ba0; bv = Bc[0] + bB0; sg = 1.0f / (1.0f + expf(-bv));
            ov0.x = xv0.x + av * sg;
            av = A[1] + ba0; bv = Bc[1] + bB0; sg = 1.0f / (1.0f + expf(-bv));
            ov0.y = xv0.y + av * sg;
            av = A[2] + ba8; bv = Bc[2] + bB8; sg = 1.0f / (1.0f + expf(-bv));
            ov8.x = xv8.x + av * sg;
            av = A[3] + ba8; bv = Bc[3] + bB8; sg = 1.0f / (1.0f + expf(-bv));
            ov8.y = xv8.y + av * sg;

            *(float2*)(Ob + (size_t)o * Ls + l) = ov0;
            *(float2*)(Ob + (size_t)(o + 8) * Ls + l) = ov8;
        }
    }
}

// ---------------------------------------------------------------------------
extern "C" void kernel_launch(void* const* d_in, const int* in_sizes, int n_in,
                              void* d_out, int out_size)
{
    const float* x      = (const float*)d_in[0];
    const float* alpha1 = (const float*)d_in[1];
    const float* log_dt = (const float*)d_in[2];
    const float* Ar     = (const float*)d_in[3];
    const float* Ai     = (const float*)d_in[4];
    const float* Cr     = (const float*)d_in[5];
    const float* Ci     = (const float*)d_in[6];
    const float* D      = (const float*)d_in[7];
    const float* alpha2 = (const float*)d_in[8];
    const float* W      = (const float*)d_in[9];
    const float* bconv  = (const float*)d_in[10];
    float* out = (float*)d_out;

    param_kernel<<<(Hd * Nm + 255) / 256, 256>>>(log_dt, Ar, Ai, Cr, Ci);
    wconv_kernel<<<(2 * Hd * Hd + 255) / 256, 256>>>(W);

    // 4096 sequences, one warp each, 8 warps/block
    scan_kernel<<<(Bsz * Hd) / 8, 256>>>(x, alpha1, alpha2, D);

    dim3 grid(Ls / 128, Hd / 64, Bsz);
    gemm_glu_kernel<<<grid, 256>>>(bconv, x, out);
}

// round 6
// speedup vs baseline: 1.3117x; 1.3117x over previous
#include <cuda_runtime.h>
#include <math.h>
#include <stdint.h>

// Problem constants
#define Bsz 8
#define Hd  512
#define Ls  4096
#define Nm  32

// Scratch (allocation-free rule: __device__ globals)
__device__ float    g_lr[Hd * Nm];
__device__ float    g_li[Hd * Nm];
__device__ float    g_wr[Hd * Nm];
__device__ float    g_wi[Hd * Nm];
__device__ float    g_dtar[Hd * Nm];
__device__ float    g_dtai[Hd * Nm];
__device__ float    g_Kt[Hd * Nm];                  // kernel taps K[h][d], d=0..31
__device__ uint32_t g_Pr[Hd * 1024];                // tf32 bits, [h][j*32+n] = Re(w λ^{j+1})
__device__ uint32_t g_Pin[Hd * 1024];               // tf32 bits, -Im(w λ^{j+1})
__device__ uint32_t g_Lr[Hd * 1024];                // tf32 bits, [h][n*32+i] = Re(λ^{31-i})
__device__ uint32_t g_Li[Hd * 1024];                // tf32 bits, Im(λ^{31-i})
__device__ float    g_l32r[Hd * Nm];                // Re(λ^32)
__device__ float    g_l32i[Hd * Nm];                // Im(λ^32)
__device__ uint32_t g_Wt[2 * Hd * Hd];              // W pre-converted to tf32 bits (1024x512)
__device__ uint32_t g_y[(size_t)Bsz * Hd * Ls];     // post-snake2 activations, tf32 bits (B,H,L)

__device__ __forceinline__ uint32_t f2tf32(float f) {
    uint32_t b;
    asm("cvt.rna.tf32.f32 %0, %1;" : "=r"(b) : "f"(f));
    return b;
}

// ---------------------------------------------------------------------------
// Kernel 1: discretization params.  lambda = exp(dt*A), w = 2*C*(lambda-1)/A
// ---------------------------------------------------------------------------
__global__ void param_kernel(const float* __restrict__ log_dt,
                             const float* __restrict__ Ar,
                             const float* __restrict__ Ai,
                             const float* __restrict__ Cr,
                             const float* __restrict__ Ci)
{
    int i = blockIdx.x * blockDim.x + threadIdx.x;
    if (i >= Hd * Nm) return;
    int h = i >> 5;
    float dt = expf(log_dt[h]);
    float ar = Ar[i], ai = Ai[i];
    float er = expf(dt * ar);
    float lr = er * cosf(dt * ai);
    float li = er * sinf(dt * ai);
    float nr = lr - 1.0f, ni = li;
    float inv = 1.0f / (ar * ar + ai * ai);
    float qr = (nr * ar + ni * ai) * inv;
    float qi = (ni * ar - nr * ai) * inv;
    float cr = Cr[i], ci = Ci[i];
    g_lr[i] = lr;
    g_li[i] = li;
    g_wr[i] = 2.0f * (cr * qr - ci * qi);
    g_wi[i] = 2.0f * (cr * qi + ci * qr);
    g_dtar[i] = dt * ar;
    g_dtai[i] = dt * ai;
}

// ---------------------------------------------------------------------------
// Kernel 1b: per-h chunk matrices: P = w*lambda^{j+1}, Lam = lambda^{31-i},
// K taps, lambda^32.  One block per h.
// ---------------------------------------------------------------------------
__global__ void param2_kernel()
{
    int h = blockIdx.x;
    int tid = threadIdx.x;
    const float* dtar = g_dtar + h * 32;
    const float* dtai = g_dtai + h * 32;
    const float* wr   = g_wr + h * 32;
    const float* wi   = g_wi + h * 32;

    for (int q = tid; q < 1024; q += blockDim.x) {
        // P entries: j = q>>5, n = q&31, power j+1
        int j = q >> 5, n = q & 31;
        float p = (float)(j + 1);
        float e = expf(p * dtar[n]);
        float ss, cc;
        sincosf(p * dtai[n], &ss, &cc);
        float lpr = e * cc, lpi = e * ss;
        float pr = wr[n] * lpr - wi[n] * lpi;
        float pi = wr[n] * lpi + wi[n] * lpr;
        g_Pr[h * 1024 + q]  = f2tf32(pr);
        g_Pin[h * 1024 + q] = f2tf32(-pi);
        // Lambda entries: row n2 = q>>5, col i = q&31, power 31-i
        int n2 = j, i = n;
        float p2 = (float)(31 - i);
        float e2 = expf(p2 * dtar[n2]);
        sincosf(p2 * dtai[n2], &ss, &cc);
        g_Lr[h * 1024 + q] = f2tf32(e2 * cc);
        g_Li[h * 1024 + q] = f2tf32(e2 * ss);
    }
    if (tid < 32) {
        // lambda^32 for mode tid
        float e = expf(32.0f * dtar[tid]);
        float ss, cc;
        sincosf(32.0f * dtai[tid], &ss, &cc);
        g_l32r[h * 32 + tid] = e * cc;
        g_l32i[h * 32 + tid] = e * ss;
        // K tap d = tid: K[d] = sum_n Re(w_n lambda_n^d)   (factor 2 inside w)
        int d = tid;
        float acc = 0.0f;
        for (int n = 0; n < 32; ++n) {
            float e2 = expf((float)d * dtar[n]);
            sincosf((float)d * dtai[n], &ss, &cc);
            acc += wr[n] * (e2 * cc) - wi[n] * (e2 * ss);
        }
        g_Kt[h * 32 + d] = acc;
    }
}

// ---------------------------------------------------------------------------
// Kernel 1c: W -> tf32 once.
// ---------------------------------------------------------------------------
__global__ void wconv_kernel(const float* __restrict__ W)
{
    int i = blockIdx.x * blockDim.x + threadIdx.x;
    if (i >= 2 * Hd * Hd) return;
    g_Wt[i] = f2tf32(W[i]);
}

// ---------------------------------------------------------------------------
// tf32 mma.sync helper (validated fragment layout, R5)
// ---------------------------------------------------------------------------
__device__ __forceinline__ void mma_tf32(float* c,
                                         uint32_t a0, uint32_t a1, uint32_t a2, uint32_t a3,
                                         uint32_t b0, uint32_t b1)
{
    asm volatile(
        "mma.sync.aligned.m16n8k8.row.col.f32.tf32.tf32.f32 "
        "{%0,%1,%2,%3}, {%4,%5,%6,%7}, {%8,%9}, {%0,%1,%2,%3};\n"
        : "+f"(c[0]), "+f"(c[1]), "+f"(c[2]), "+f"(c[3])
        : "r"(a0), "r"(a1), "r"(a2), "r"(a3), "r"(b0), "r"(b1));
}

// ---------------------------------------------------------------------------
// Kernel 2: tensor-core chunked scan.
// One warp per h, all 8 batches together.  Per 32-step chunk:
//   Y(32t x 8b) = T@U + Pr@Sr + (-Pi)@Si        (24 mmas, one C accumulator)
//   LU = Lam@U (complex, 16 mmas);  S_new = diag(l32)*S_old + LU   (fp32)
// snake1 on input, snake2 + D-skip on output; y stored as tf32 bits.
// 2 warps / block, static smem 25.6KB.
// ---------------------------------------------------------------------------
__global__ __launch_bounds__(64)
void scan2_kernel(const float* __restrict__ x,
                  const float* __restrict__ alpha1,
                  const float* __restrict__ alpha2,
                  const float* __restrict__ Dp)
{
    __shared__ uint32_t sPr[2][32 * 36];
    __shared__ uint32_t sPin[2][32 * 36];
    __shared__ float    sU[2][32 * 9];
    __shared__ uint32_t sSr[2][32 * 9];
    __shared__ uint32_t sSi[2][32 * 9];
    __shared__ float    sK[2][32];

    const int tid  = threadIdx.x;
    const int wp   = tid >> 5;
    const int lane = tid & 31;
    const int g    = lane >> 2;       // 0..7
    const int t4   = lane & 3;        // 0..3
    const int h    = blockIdx.x * 2 + wp;

    // ---- stage P into smem (stride 36 words -> conflict-free frag LDS) ----
    for (int q = lane; q < 1024; q += 32) {
        int j = q >> 5, n = q & 31;
        sPr[wp][j * 36 + n]  = g_Pr[h * 1024 + q];
        sPin[wp][j * 36 + n] = g_Pin[h * 1024 + q];
    }
    sK[wp][lane] = g_Kt[h * 32 + lane];
    __syncwarp();

    // ---- T fragments from K taps (Toeplitz, lower-triangular) ----
    uint32_t Tf[2][4][4];
    #pragma unroll
    for (int hh = 0; hh < 2; ++hh)
        #pragma unroll
        for (int kc = 0; kc < 4; ++kc) {
            int row = hh * 16 + g;
            int col = kc * 8 + t4;
            int d0 = row - col, d1 = row + 8 - col, d2 = row - col - 4, d3 = row + 8 - col - 4;
            Tf[hh][kc][0] = (d0 >= 0) ? f2tf32(sK[wp][d0]) : 0u;
            Tf[hh][kc][1] = (d1 >= 0) ? f2tf32(sK[wp][d1]) : 0u;
            Tf[hh][kc][2] = (d2 >= 0) ? f2tf32(sK[wp][d2]) : 0u;
            Tf[hh][kc][3] = (d3 >= 0) ? f2tf32(sK[wp][d3]) : 0u;
        }

    // ---- Lambda fragments (persistent in regs) ----
    uint32_t Lrf[2][4][4], Lif[2][4][4];
    #pragma unroll
    for (int hh = 0; hh < 2; ++hh)
        #pragma unroll
        for (int kc = 0; kc < 4; ++kc) {
            int base = h * 1024 + (hh * 16 + g) * 32 + kc * 8 + t4;
            Lrf[hh][kc][0] = g_Lr[base];
            Lrf[hh][kc][1] = g_Lr[base + 256];
            Lrf[hh][kc][2] = g_Lr[base + 4];
            Lrf[hh][kc][3] = g_Lr[base + 260];
            Lif[hh][kc][0] = g_Li[base];
            Lif[hh][kc][1] = g_Li[base + 256];
            Lif[hh][kc][2] = g_Li[base + 4];
            Lif[hh][kc][3] = g_Li[base + 260];
        }

    // ---- lambda^32 for this lane's 4 modes (g + 8*mi) ----
    float l32r4[4], l32i4[4];
    #pragma unroll
    for (int mi = 0; mi < 4; ++mi) {
        l32r4[mi] = g_l32r[h * 32 + g + 8 * mi];
        l32i4[mi] = g_l32i[h * 32 + g + 8 * mi];
    }

    const float a1v  = alpha1[h];
    const float inv1 = 1.0f / (a1v + 1e-9f);
    const float a2v  = alpha2[h];
    const float inv2 = 1.0f / (a2v + 1e-9f);
    const float Dh   = Dp[h];

    // lane-fixed bases
    const float* xbh = x + ((size_t)g * Hd + h) * Ls;                 // batch g
    uint32_t* yb0 = g_y + ((size_t)(2 * t4)     * Hd + h) * Ls;       // batch 2*t4
    uint32_t* yb1 = g_y + ((size_t)(2 * t4 + 1) * Hd + h) * Ls;       // batch 2*t4+1

    // state
    float    Scr[8], Sci[8];
    uint32_t SrB[8], SiB[8];
    #pragma unroll
    for (int i = 0; i < 8; ++i) { Scr[i] = 0.0f; Sci[i] = 0.0f; SrB[i] = 0u; SiB[i] = 0u; }

    #pragma unroll 1
    for (int l0 = 0; l0 < Ls; l0 += 32) {
        // 1. input: snake1, build U B-fragments + u tile
        uint32_t uB[8];
        #pragma unroll
        for (int kc = 0; kc < 4; ++kc)
            #pragma unroll
            for (int r = 0; r < 2; ++r) {
                int t = kc * 8 + t4 + r * 4;
                float xv = xbh[l0 + t];
                float sn = __sinf(a1v * xv);
                float u  = fmaf(sn * sn, inv1, xv);
                sU[wp][t * 9 + g] = u;
                uB[kc * 2 + r] = f2tf32(u);
            }
        __syncwarp();

        // 2. u in C layout (for D-skip)
        float uC[8];
        #pragma unroll
        for (int hh = 0; hh < 2; ++hh)
            #pragma unroll
            for (int cc = 0; cc < 4; ++cc) {
                int row = hh * 16 + g + ((cc >> 1) << 3);
                int col = 2 * t4 + (cc & 1);
                uC[hh * 4 + cc] = sU[wp][row * 9 + col];
            }

        // 3. Y = T@U + Pr@Sr + Pin@Si
        float yC[8];
        #pragma unroll
        for (int i = 0; i < 8; ++i) yC[i] = 0.0f;
        #pragma unroll
        for (int kc = 0; kc < 4; ++kc)
            #pragma unroll
            for (int hh = 0; hh < 2; ++hh)
                mma_tf32(yC + hh * 4, Tf[hh][kc][0], Tf[hh][kc][1], Tf[hh][kc][2], Tf[hh][kc][3],
                         uB[kc * 2], uB[kc * 2 + 1]);
        #pragma unroll
        for (int kc = 0; kc < 4; ++kc)
            #pragma unroll
            for (int hh = 0; hh < 2; ++hh) {
                int base = (hh * 16 + g) * 36 + kc * 8 + t4;
                uint32_t p0 = sPr[wp][base],       p1 = sPr[wp][base + 288];
                uint32_t p2 = sPr[wp][base + 4],   p3 = sPr[wp][base + 292];
                mma_tf32(yC + hh * 4, p0, p1, p2, p3, SrB[kc * 2], SrB[kc * 2 + 1]);
                uint32_t q0 = sPin[wp][base],      q1 = sPin[wp][base + 288];
                uint32_t q2 = sPin[wp][base + 4],  q3 = sPin[wp][base + 292];
                mma_tf32(yC + hh * 4, q0, q1, q2, q3, SiB[kc * 2], SiB[kc * 2 + 1]);
            }

        // 4. LU = Lambda @ U (complex out, fp32 accum)
        float Ur[8], Ui[8];
        #pragma unroll
        for (int i = 0; i < 8; ++i) { Ur[i] = 0.0f; Ui[i] = 0.0f; }
        #pragma unroll
        for (int kc = 0; kc < 4; ++kc)
            #pragma unroll
            for (int hh = 0; hh < 2; ++hh) {
                mma_tf32(Ur + hh * 4, Lrf[hh][kc][0], Lrf[hh][kc][1], Lrf[hh][kc][2], Lrf[hh][kc][3],
                         uB[kc * 2], uB[kc * 2 + 1]);
                mma_tf32(Ui + hh * 4, Lif[hh][kc][0], Lif[hh][kc][1], Lif[hh][kc][2], Lif[hh][kc][3],
                         uB[kc * 2], uB[kc * 2 + 1]);
            }

        // 5. state update (fp32 chain) + store tf32 copy for next chunk's carry
        #pragma unroll
        for (int idx = 0; idx < 8; ++idx) {
            int hh = idx >> 2, cc = idx & 3;
            int mi = hh * 2 + (cc >> 1);
            float sr = Scr[idx], si = Sci[idx];
            float nr = fmaf(l32r4[mi], sr, fmaf(-l32i4[mi], si, Ur[idx]));
            float ni = fmaf(l32r4[mi], si, fmaf(l32i4[mi], sr, Ui[idx]));
            Scr[idx] = nr; Sci[idx] = ni;
            int row = g + 8 * mi;
            int col = 2 * t4 + (cc & 1);
            sSr[wp][row * 9 + col] = f2tf32(nr);
            sSi[wp][row * 9 + col] = f2tf32(ni);
        }
        __syncwarp();

        // 6. reload S as B-fragments (k = mode)
        #pragma unroll
        for (int kc = 0; kc < 4; ++kc)
            #pragma unroll
            for (int r = 0; r < 2; ++r) {
                int m = kc * 8 + t4 + r * 4;
                SrB[kc * 2 + r] = sSr[wp][m * 9 + g];
                SiB[kc * 2 + r] = sSi[wp][m * 9 + g];
            }

        // 7. epilogue: D-skip, snake2, store tf32 bits
        #pragma unroll
        for (int idx = 0; idx < 8; ++idx) {
            int hh = idx >> 2, cc = idx & 3;
            int row = hh * 16 + g + ((cc >> 1) << 3);      // time within chunk
            float yv = fmaf(uC[idx], Dh, yC[idx]);
            float s2 = __sinf(a2v * yv);
            yv = fmaf(s2 * s2, inv2, yv);
            uint32_t bits = f2tf32(yv);
            if (cc & 1) yb1[l0 + row] = bits;
            else        yb0[l0 + row] = bits;
        }
        __syncwarp();
    }
}

// ---------------------------------------------------------------------------
// Kernel 3: fused 1x1 conv GEMM (tf32 mma.sync) + GLU + residual (unchanged)
// ---------------------------------------------------------------------------
#define BK 16
#define SWS (BK + 4)
#define SYS (128 + 8)

__device__ __forceinline__ void cp_async16(uint32_t smem, const void* gmem) {
    asm volatile("cp.async.cg.shared.global [%0], [%1], 16;\n" :: "r"(smem), "l"(gmem));
}
__device__ __forceinline__ void cp_commit() {
    asm volatile("cp.async.commit_group;\n");
}
template <int N> __device__ __forceinline__ void cp_wait() {
    asm volatile("cp.async.wait_group %0;\n" :: "n"(N));
}

__global__ __launch_bounds__(256, 2)
void gemm_glu_kernel(const float* __restrict__ bias,
                     const float* __restrict__ X,
                     float* __restrict__ out)
{
    __shared__ uint32_t sW[2][128][SWS];
    __shared__ uint32_t sY[2][BK][SYS];

    const int tid = threadIdx.x;
    const int lane = tid & 31;
    const int wid = tid >> 5;
    const int wm = wid >> 2;
    const int wn = wid & 3;
    const int t4 = lane & 3;
    const int g  = lane >> 2;

    const int l0 = blockIdx.x * 128;
    const int r0 = blockIdx.y * 64;
    const int bb = blockIdx.z;

    const uint32_t* Yb = g_y + (size_t)bb * Hd * Ls;

    const uint32_t swb = (uint32_t)__cvta_generic_to_shared(&sW[0][0][0]);
    const uint32_t syb = (uint32_t)__cvta_generic_to_shared(&sY[0][0][0]);

    int wf0 = tid, wf1 = tid + 256;
    int wrow0 = wf0 >> 2, wc0 = (wf0 & 3) << 2;
    int wrow1 = wf1 >> 2, wc1 = (wf1 & 3) << 2;
    int wsrc0 = (r0 + wrow0 + (wrow0 >= 64 ? 448 : 0)) * Hd;
    int wsrc1 = (r0 + wrow1 + (wrow1 >= 64 ? 448 : 0)) * Hd;
    int yk0 = wf0 >> 5, yc0 = (wf0 & 31) << 2;
    int yk1 = wf1 >> 5, yc1 = (wf1 & 31) << 2;

    float acc[2][2][4][4];
    #pragma unroll
    for (int a = 0; a < 2; ++a)
        #pragma unroll
        for (int m = 0; m < 2; ++m)
            #pragma unroll
            for (int n = 0; n < 4; ++n)
                #pragma unroll
                for (int q = 0; q < 4; ++q) acc[a][m][n][q] = 0.0f;

    #define LOAD_CHUNK(KC, BUF) do {                                              \
        int _k0 = (KC) * BK;                                                      \
        cp_async16(swb + (((BUF)*128 + wrow0) * SWS + wc0) * 4,                   \
                   g_Wt + wsrc0 + _k0 + wc0);                                     \
        cp_async16(swb + (((BUF)*128 + wrow1) * SWS + wc1) * 4,                   \
                   g_Wt + wsrc1 + _k0 + wc1);                                     \
        cp_async16(syb + (((BUF)*BK + yk0) * SYS + yc0) * 4,                      \
                   Yb + (size_t)(_k0 + yk0) * Ls + l0 + yc0);                     \
        cp_async16(syb + (((BUF)*BK + yk1) * SYS + yc1) * 4,                      \
                   Yb + (size_t)(_k0 + yk1) * Ls + l0 + yc1);                     \
    } while (0)

    LOAD_CHUNK(0, 0); cp_commit();
    LOAD_CHUNK(1, 1); cp_commit();

    const int NCH = Hd / BK;
    #pragma unroll 1
    for (int kc = 0; kc < NCH; ++kc) {
        if (kc < NCH - 1) cp_wait<1>(); else cp_wait<0>();
        __syncthreads();
        int buf = kc & 1;

        #pragma unroll
        for (int ks = 0; ks < 2; ++ks) {
            int kk = ks * 8 + t4;
            uint32_t B0[4], B1[4];
            #pragma unroll
            for (int ni = 0; ni < 4; ++ni) {
                int col = wn * 32 + ni * 8 + g;
                B0[ni] = sY[buf][kk][col];
                B1[ni] = sY[buf][kk + 4][col];
            }
            #pragma unroll
            for (int half = 0; half < 2; ++half) {
                #pragma unroll
                for (int mi = 0; mi < 2; ++mi) {
                    int rb = half * 64 + wm * 32 + mi * 16 + g;
                    uint32_t a0 = sW[buf][rb][kk];
                    uint32_t a1 = sW[buf][rb + 8][kk];
                    uint32_t a2 = sW[buf][rb][kk + 4];
                    uint32_t a3 = sW[buf][rb + 8][kk + 4];
                    #pragma unroll
                    for (int ni = 0; ni < 4; ++ni)
                        mma_tf32(acc[half][mi][ni], a0, a1, a2, a3, B0[ni], B1[ni]);
                }
            }
        }
        __syncthreads();
        if (kc + 2 < NCH) { LOAD_CHUNK(kc + 2, buf); cp_commit(); }
    }
    #undef LOAD_CHUNK

    const float* Xb = X   + (size_t)bb * Hd * Ls;
    float*       Ob = out + (size_t)bb * Hd * Ls;

    #pragma unroll
    for (int mi = 0; mi < 2; ++mi) {
        int o = r0 + wm * 32 + mi * 16 + g;
        float ba0 = bias[o];
        float bB0 = bias[o + 512];
        float ba8 = bias[o + 8];
        float bB8 = bias[o + 520];
        #pragma unroll
        for (int ni = 0; ni < 4; ++ni) {
            int l = l0 + wn * 32 + ni * 8 + 2 * t4;
            const float* A = acc[0][mi][ni];
            const float* Bc = acc[1][mi][ni];

            float2 xv0 = *(const float2*)(Xb + (size_t)o * Ls + l);
            float2 xv8 = *(const float2*)(Xb + (size_t)(o + 8) * Ls + l);

            float av, bv, sg;
            float2 ov0, ov8;
            av = A[0] + ba0; bv = Bc[0] + bB0; sg = 1.0f / (1.0f + expf(-bv));
            ov0.x = xv0.x + av * sg;
            av = A[1] + ba0; bv = Bc[1] + bB0; sg = 1.0f / (1.0f + expf(-bv));
            ov0.y = xv0.y + av * sg;
            av = A[2] + ba8; bv = Bc[2] + bB8; sg = 1.0f / (1.0f + expf(-bv));
            ov8.x = xv8.x + av * sg;
            av = A[3] + ba8; bv = Bc[3] + bB8; sg = 1.0f / (1.0f + expf(-bv));
            ov8.y = xv8.y + av * sg;

            *(float2*)(Ob + (size_t)o * Ls + l) = ov0;
            *(float2*)(Ob + (size_t)(o + 8) * Ls + l) = ov8;
        }
    }
}

// ---------------------------------------------------------------------------
extern "C" void kernel_launch(void* const* d_in, const int* in_sizes, int n_in,
                              void* d_out, int out_size)
{
    const float* x      = (const float*)d_in[0];
    const float* alpha1 = (const float*)d_in[1];
    const float* log_dt = (const float*)d_in[2];
    const float* Ar     = (const float*)d_in[3];
    const float* Ai     = (const float*)d_in[4];
    const float* Cr     = (const float*)d_in[5];
    const float* Ci     = (const float*)d_in[6];
    const float* D      = (const float*)d_in[7];
    const float* alpha2 = (const float*)d_in[8];
    const float* W      = (const float*)d_in[9];
    const float* bconv  = (const float*)d_in[10];
    float* out = (float*)d_out;

    param_kernel<<<(Hd * Nm + 255) / 256, 256>>>(log_dt, Ar, Ai, Cr, Ci);
    param2_kernel<<<Hd, 256>>>();
    wconv_kernel<<<(2 * Hd * Hd + 255) / 256, 256>>>(W);

    // tensor-core chunked scan: 1 warp per h, 2 warps per block
    scan2_kernel<<<Hd / 2, 64>>>(x, alpha1, alpha2, D);

    dim3 grid(Ls / 128, Hd / 64, Bsz);
    gemm_glu_kernel<<<grid, 256>>>(bconv, x, out);
}